// round 4
// baseline (speedup 1.0000x reference)
#include <cuda_runtime.h>
#include <cstdint>

#define B 256
#define S 512
#define IN_F 32
#define H 256
#define G3 768
#define D_OUT 32
#define NSTATE 4
#define PRED 96

#define GRU_CTAS 128
#define CLUSTER_W 8            // 8 strip-CTAs per rowtile form one cluster
#define SW_STRIDE 260          // % 32 == 4 -> conflict-free LDS.128 per 8-lane phase
#define SH_STRIDE 256
#define W_FLOATS (96 * SW_STRIDE)              // 24960
#define HBUF_FLOATS (16 * SH_STRIDE)           // 4096
#define SMEM_FLOATS (W_FLOATS + 2 * HBUF_FLOATS)
#define SMEM_BYTES (SMEM_FLOATS * 4)           // 132608 B

// -------- packed f32x2 helpers --------
__device__ __forceinline__ unsigned long long fma2(unsigned long long a,
                                                   unsigned long long b,
                                                   unsigned long long c)
{
    unsigned long long d;
    asm("fma.rn.f32x2 %0, %1, %2, %3;" : "=l"(d) : "l"(a), "l"(b), "l"(c));
    return d;
}
__device__ __forceinline__ unsigned long long dup2(float x)
{
    unsigned long long d;
    unsigned r = __float_as_uint(x);
    asm("mov.b64 %0, {%1, %1};" : "=l"(d) : "r"(r));
    return d;
}
__device__ __forceinline__ float hsum2(unsigned long long a)
{
    unsigned lo, hi;
    asm("mov.b64 {%0, %1}, %2;" : "=r"(lo), "=r"(hi) : "l"(a));
    return __uint_as_float(lo) + __uint_as_float(hi);
}
__device__ __forceinline__ void unpack2(unsigned long long a, float& lo, float& hi)
{
    unsigned l, h;
    asm("mov.b64 {%0, %1}, %2;" : "=r"(l), "=r"(h) : "l"(a));
    lo = __uint_as_float(l); hi = __uint_as_float(h);
}
__device__ __forceinline__ float tanh_ap(float x)
{
    float y;
    asm("tanh.approx.f32 %0, %1;" : "=f"(y) : "f"(x));
    return y;
}
__device__ __forceinline__ float sigmoid_ap(float x)
{
    return 0.5f * tanh_ap(0.5f * x) + 0.5f;
}

// -------- cluster helpers --------
__device__ __forceinline__ uint32_t smem_u32(const void* p)
{
    uint32_t a;
    asm("{ .reg .u64 t; cvta.to.shared.u64 t, %1; cvt.u32.u64 %0, t; }"
        : "=r"(a) : "l"(p));
    return a;
}
__device__ __forceinline__ uint32_t mapa_rank(uint32_t laddr, uint32_t rank)
{
    uint32_t r;
    asm("mapa.shared::cluster.u32 %0, %1, %2;" : "=r"(r) : "r"(laddr), "r"(rank));
    return r;
}
__device__ __forceinline__ void st_cluster_f32(uint32_t addr, float v)
{
    asm volatile("st.shared::cluster.f32 [%0], %1;" :: "r"(addr), "f"(v) : "memory");
}
__device__ __forceinline__ void cluster_arrive_wait()
{
    asm volatile("barrier.cluster.arrive.aligned;" ::: "memory");
    asm volatile("barrier.cluster.wait.aligned;" ::: "memory");
}

// -------- scratch --------
__device__ float g_xp[(size_t)B * S * G3];
__device__ float g_h1s[(size_t)B * S * H];
__device__ float g_h2[B * H];

// -------- SGEMM: out[M,N] = A[M,K] @ W[N,K]^T + bias[N] --------
// Tile 128(M) x 64(N), 256 threads, 8x4 micro-tile, packed f32x2.
__global__ __launch_bounds__(256) void gemm_nt_bias(
    const float* __restrict__ A, const float* __restrict__ W,
    const float* __restrict__ bias, float* __restrict__ out,
    int M, int N, int K)
{
    __shared__ float As[16 * 128];   // [k][m]
    __shared__ float Ws[16 * 64];    // [k][n]
    const int n0 = blockIdx.x * 64;
    const int m0 = blockIdx.y * 128;
    const int tid = threadIdx.x;
    const int tx = tid & 15;
    const int ty = tid >> 4;
    const int war = tid & 63;
    const int wak = (tid >> 6) << 2;

    unsigned long long acc[8][2];
#pragma unroll
    for (int i = 0; i < 8; i++) { acc[i][0] = 0ull; acc[i][1] = 0ull; }

    for (int k0 = 0; k0 < K; k0 += 16) {
#pragma unroll
        for (int r = 0; r < 2; r++) {
            int f4id = r * 256 + tid;
            int ar = f4id & 127;
            int ak = (f4id >> 7) << 2;
            float4 a = *(const float4*)&A[(size_t)(m0 + ar) * K + k0 + ak];
            As[(ak + 0) * 128 + ar] = a.x;
            As[(ak + 1) * 128 + ar] = a.y;
            As[(ak + 2) * 128 + ar] = a.z;
            As[(ak + 3) * 128 + ar] = a.w;
        }
        {
            float4 w = *(const float4*)&W[(size_t)(n0 + war) * K + k0 + wak];
            Ws[(wak + 0) * 64 + war] = w.x;
            Ws[(wak + 1) * 64 + war] = w.y;
            Ws[(wak + 2) * 64 + war] = w.z;
            Ws[(wak + 3) * 64 + war] = w.w;
        }
        __syncthreads();
#pragma unroll
        for (int k = 0; k < 16; k++) {
            float4 av0 = *(const float4*)&As[k * 128 + ty * 8];
            float4 av1 = *(const float4*)&As[k * 128 + ty * 8 + 4];
            ulonglong2 wv = *(const ulonglong2*)&Ws[k * 64 + tx * 4];
            float am[8] = {av0.x, av0.y, av0.z, av0.w, av1.x, av1.y, av1.z, av1.w};
#pragma unroll
            for (int i = 0; i < 8; i++) {
                unsigned long long ai = dup2(am[i]);
                acc[i][0] = fma2(ai, wv.x, acc[i][0]);
                acc[i][1] = fma2(ai, wv.y, acc[i][1]);
            }
        }
        __syncthreads();
    }

    float4 bv = *(const float4*)&bias[n0 + tx * 4];
#pragma unroll
    for (int i = 0; i < 8; i++) {
        int m = m0 + ty * 8 + i;
        float c0, c1, c2, c3;
        unpack2(acc[i][0], c0, c1);
        unpack2(acc[i][1], c2, c3);
        float4 o;
        o.x = c0 + bv.x; o.y = c1 + bv.y; o.z = c2 + bv.z; o.w = c3 + bv.w;
        *(float4*)&out[(size_t)m * N + n0 + tx * 4] = o;
    }
}

// -------- persistent GRU layer, cluster edition --------
// Grid 128 = 16 rowtiles x 8 strips; each rowtile's 8 strips = one 8-CTA cluster.
// h is double-buffered in smem; new h slices are broadcast to all cluster peers
// via st.shared::cluster; one barrier.cluster per step. No gmem h, no atomics.
__global__ __launch_bounds__(128, 1) __cluster_dims__(CLUSTER_W, 1, 1)
void gru_layer(
    const float* __restrict__ xp,   // [B*S, 768] = x-proj incl. b_ih
    const float* __restrict__ Whh,  // [768, 256]
    const float* __restrict__ bhh,  // [768]
    float* __restrict__ h_seq,      // [B*S, 256] or null
    float* __restrict__ h_final)    // [B, 256] or null
{
    extern __shared__ float sm[];
    float* sW = sm;                        // [96][SW_STRIDE]
    float* sHb = sm + W_FLOATS;            // [2][16][256]

    const int cta = blockIdx.x;
    const int rowtile = cta >> 3;
    const uint32_t strip = cta & 7;        // == cluster rank (1-D cluster)
    const int j0 = (int)strip * 32;
    const int r0 = rowtile * 16;
    const int tid = threadIdx.x;
    const int j = tid & 31;                // col within strip
    const int rq = tid >> 5;               // warp: rows rq*4..+3
    const int jj = j0 + j;

    // Preload W_hh strip (96 rows x 256) once.
    for (int i = tid; i < 96 * 64; i += 128) {
        int wrow = i >> 6;
        int k4 = (i & 63) << 2;
        int g = wrow >> 5, jc = wrow & 31;
        float4 v = *(const float4*)&Whh[(size_t)(g * H + j0 + jc) * H + k4];
        *(float4*)&sW[wrow * SW_STRIDE + k4] = v;
    }
    const float bhr = bhh[jj];
    const float bhz = bhh[H + jj];
    const float bhn = bhh[2 * H + jj];

    // Zero h buffer 0 (full 16x256 local copy).
    for (int i = tid; i < HBUF_FLOATS; i += 128) sHb[i] = 0.f;
    __syncthreads();

    // Hoisted peer base addresses (byte address of sHb in each peer's smem).
    const uint32_t myHb = smem_u32(sHb);
    uint32_t pb[CLUSTER_W];
#pragma unroll
    for (int p = 0; p < CLUSTER_W; p++) pb[p] = mapa_rank(myHb, (uint32_t)p);

    cluster_arrive_wait();   // buffers zeroed cluster-wide before any step

    const float* wr = sW + j * SW_STRIDE;
    const float* wz = sW + (32 + j) * SW_STRIDE;
    const float* wn = sW + (64 + j) * SW_STRIDE;

    for (int t = 0; t < S; t++) {
        const float* hRead = sHb + (t & 1) * HBUF_FLOATS;
        const uint32_t wOffBase = ((uint32_t)(((t + 1) & 1) * HBUF_FLOATS)) * 4u;

        // Prefetch this step's xp values (independent of h; hides gmem latency).
        float pxr[4], pxz[4], pxn[4];
#pragma unroll
        for (int i = 0; i < 4; i++) {
            size_t xb = ((size_t)(r0 + rq * 4 + i) * S + t) * G3 + jj;
            pxr[i] = __ldg(&xp[xb]);
            pxz[i] = __ldg(&xp[xb + H]);
            pxn[i] = __ldg(&xp[xb + 2 * H]);
        }

        unsigned long long ar2[4], az2[4], an2[4];
#pragma unroll
        for (int i = 0; i < 4; i++) { ar2[i] = 0ull; az2[i] = 0ull; an2[i] = 0ull; }

        const float* hb = hRead + rq * 4 * SH_STRIDE;

#pragma unroll 8
        for (int k = 0; k < H; k += 4) {
            ulonglong2 wrv = *(const ulonglong2*)(wr + k);
            ulonglong2 wzv = *(const ulonglong2*)(wz + k);
            ulonglong2 wnv = *(const ulonglong2*)(wn + k);
#pragma unroll
            for (int i = 0; i < 4; i++) {
                ulonglong2 hv = *(const ulonglong2*)(hb + i * SH_STRIDE + k); // broadcast
                ar2[i] = fma2(hv.x, wrv.x, ar2[i]);
                az2[i] = fma2(hv.x, wzv.x, az2[i]);
                an2[i] = fma2(hv.x, wnv.x, an2[i]);
                ar2[i] = fma2(hv.y, wrv.y, ar2[i]);
                az2[i] = fma2(hv.y, wzv.y, az2[i]);
                an2[i] = fma2(hv.y, wnv.y, an2[i]);
            }
        }

#pragma unroll
        for (int i = 0; i < 4; i++) {
            int rloc = rq * 4 + i;
            int row = r0 + rloc;
            float rg = sigmoid_ap(pxr[i] + hsum2(ar2[i]) + bhr);
            float zg = sigmoid_ap(pxz[i] + hsum2(az2[i]) + bhz);
            float ng = tanh_ap(pxn[i] + rg * (hsum2(an2[i]) + bhn));
            float hold = hRead[rloc * SH_STRIDE + jj];
            float hnew = (1.f - zg) * ng + zg * hold;

            // Broadcast hnew into all 8 cluster CTAs' write buffer.
            uint32_t off = wOffBase + ((uint32_t)(rloc * SH_STRIDE + jj)) * 4u;
#pragma unroll
            for (int p = 0; p < CLUSTER_W; p++)
                st_cluster_f32(pb[p] + off, hnew);

            if (h_seq) h_seq[((size_t)row * S + t) * H + jj] = hnew;
            if (h_final && t == S - 1) h_final[(size_t)row * H + jj] = hnew;
        }

        // One cluster barrier per step (release/acquire orders the peer stores).
        cluster_arrive_wait();
    }
}

// -------- projection + 96-step diagonal forecast, fused --------
__global__ void forecast_kernel(
    const float* __restrict__ h2, const float* __restrict__ Wp,
    const float* __restrict__ bp, const float* __restrict__ C,
    const float* __restrict__ rld, const float* __restrict__ rtd,
    const float* __restrict__ rg_, const float* __restrict__ om,
    float* __restrict__ out)
{
    const int b = blockIdx.x;
    const int d = threadIdx.x;
    __shared__ float sh[H];
    for (int i = d; i < H; i += 32) sh[i] = h2[(size_t)b * H + i];
    __syncthreads();

    float s[NSTATE];
#pragma unroll
    for (int st = 0; st < NSTATE; st++) {
        const float* w = Wp + (size_t)(d * NSTATE + st) * H;
        float acc = bp[d * NSTATE + st];
        for (int k = 0; k < H; k += 4) {
            float4 wv = *(const float4*)(w + k);
            acc += sh[k] * wv.x + sh[k + 1] * wv.y + sh[k + 2] * wv.z + sh[k + 3] * wv.w;
        }
        s[st] = acc;
    }

    float al = 1.f / (1.f + expf(-rld[d])) * 0.15f + 0.85f;
    float at = 1.f / (1.f + expf(-rtd[d])) * 0.25f + 0.70f;
    float gg = 1.f / (1.f + expf(-rg_[d])) * 0.20f + 0.80f;
    float cc = cosf(om[d]), sn = sinf(om[d]);
    float r00 = gg * cc, r01 = -gg * sn, r10 = gg * sn, r11 = gg * cc;
    float C0 = C[d * 4 + 0], C1 = C[d * 4 + 1], C2 = C[d * 4 + 2], C3 = C[d * 4 + 3];

    for (int p = 0; p < PRED; p++) {
        float n0 = s[0] * al;
        float n1 = s[1] * at;
        float n2 = s[2] * r00 + s[3] * r10;
        float n3 = s[2] * r01 + s[3] * r11;
        s[0] = n0; s[1] = n1; s[2] = n2; s[3] = n3;
        out[((size_t)b * PRED + p) * D_OUT + d] = C0 * n0 + C1 * n1 + C2 * n2 + C3 * n3;
    }
}

extern "C" void kernel_launch(void* const* d_in, const int* in_sizes, int n_in,
                              void* d_out, int out_size)
{
    const float* x    = (const float*)d_in[0];
    const float* Wih0 = (const float*)d_in[1];
    const float* Whh0 = (const float*)d_in[2];
    const float* bih0 = (const float*)d_in[3];
    const float* bhh0 = (const float*)d_in[4];
    const float* Wih1 = (const float*)d_in[5];
    const float* Whh1 = (const float*)d_in[6];
    const float* bih1 = (const float*)d_in[7];
    const float* bhh1 = (const float*)d_in[8];
    const float* Wp   = (const float*)d_in[9];
    const float* bp   = (const float*)d_in[10];
    const float* C    = (const float*)d_in[11];
    const float* rld  = (const float*)d_in[12];
    const float* rtd  = (const float*)d_in[13];
    const float* rg   = (const float*)d_in[14];
    const float* om   = (const float*)d_in[15];
    float* out = (float*)d_out;

    float *xp, *h1s, *h2;
    cudaGetSymbolAddress((void**)&xp, g_xp);
    cudaGetSymbolAddress((void**)&h1s, g_h1s);
    cudaGetSymbolAddress((void**)&h2, g_h2);

    cudaFuncSetAttribute(gru_layer, cudaFuncAttributeMaxDynamicSharedMemorySize, SMEM_BYTES);

    dim3 gg(G3 / 64, (B * S) / 128);

    gemm_nt_bias<<<gg, 256>>>(x, Wih0, bih0, xp, B * S, G3, IN_F);
    gru_layer<<<GRU_CTAS, 128, SMEM_BYTES>>>(xp, Whh0, bhh0, h1s, nullptr);
    gemm_nt_bias<<<gg, 256>>>(h1s, Wih1, bih1, xp, B * S, G3, H);
    gru_layer<<<GRU_CTAS, 128, SMEM_BYTES>>>(xp, Whh1, bhh1, nullptr, h2);
    forecast_kernel<<<B, 32>>>(h2, Wp, bp, C, rld, rtd, rg, om, out);
}

// round 5
// speedup vs baseline: 1.1537x; 1.1537x over previous
#include <cuda_runtime.h>
#include <cstdint>

#define B 256
#define S 512
#define IN_F 32
#define H 256
#define G3 768
#define D_OUT 32
#define NSTATE 4
#define PRED 96

#define GRU_CTAS 128
#define ROWTILES 16
#define STRIPS 8
#define SW_STRIDE 260          // % 32 == 4 -> conflict-free LDS.128 per 8-lane phase
#define SH_STRIDE 256
#define W_FLOATS (96 * SW_STRIDE)      // 24960
#define H_FLOATS (16 * SH_STRIDE)      // 4096
#define RED_FLOATS (16 * 3 * 32)       // 1536
#define SMEM_FLOATS (W_FLOATS + H_FLOATS + RED_FLOATS)
#define SMEM_BYTES (SMEM_FLOATS * 4)   // 122368 B

// -------- packed f32x2 helpers --------
__device__ __forceinline__ unsigned long long fma2(unsigned long long a,
                                                   unsigned long long b,
                                                   unsigned long long c)
{
    unsigned long long d;
    asm("fma.rn.f32x2 %0, %1, %2, %3;" : "=l"(d) : "l"(a), "l"(b), "l"(c));
    return d;
}
__device__ __forceinline__ unsigned long long dup2(float x)
{
    unsigned long long d;
    unsigned r = __float_as_uint(x);
    asm("mov.b64 %0, {%1, %1};" : "=l"(d) : "r"(r));
    return d;
}
__device__ __forceinline__ float hsum2(unsigned long long a)
{
    unsigned lo, hi;
    asm("mov.b64 {%0, %1}, %2;" : "=r"(lo), "=r"(hi) : "l"(a));
    return __uint_as_float(lo) + __uint_as_float(hi);
}
__device__ __forceinline__ void unpack2(unsigned long long a, float& lo, float& hi)
{
    unsigned l, h;
    asm("mov.b64 {%0, %1}, %2;" : "=r"(l), "=r"(h) : "l"(a));
    lo = __uint_as_float(l); hi = __uint_as_float(h);
}
__device__ __forceinline__ float tanh_ap(float x)
{
    float y;
    asm("tanh.approx.f32 %0, %1;" : "=f"(y) : "f"(x));
    return y;
}
__device__ __forceinline__ float sigmoid_ap(float x)
{
    return 0.5f * tanh_ap(0.5f * x) + 0.5f;
}

// -------- release/acquire barrier primitives --------
__device__ __forceinline__ unsigned atom_add_acqrel(unsigned* p, unsigned v)
{
    unsigned old;
    asm volatile("atom.acq_rel.gpu.global.add.u32 %0, [%1], %2;"
                 : "=r"(old) : "l"(p), "r"(v) : "memory");
    return old;
}
__device__ __forceinline__ void st_release(unsigned* p, unsigned v)
{
    asm volatile("st.release.gpu.global.u32 [%0], %1;" :: "l"(p), "r"(v) : "memory");
}
__device__ __forceinline__ unsigned ld_acquire(const unsigned* p)
{
    unsigned v;
    asm volatile("ld.acquire.gpu.global.u32 %0, [%1];" : "=r"(v) : "l"(p) : "memory");
    return v;
}

// -------- scratch --------
__device__ float g_xp[(size_t)B * S * G3];
__device__ float g_h1s[(size_t)B * S * H];
__device__ float g_hbuf[2 * B * H];
__device__ float g_h2[B * H];
__device__ unsigned g_bar_count[ROWTILES];
__device__ unsigned g_bar_gen[ROWTILES];

// -------- SGEMM (R2-proven 64x64 tile): out[M,N] = A[M,K] @ W[N,K]^T + bias --------
__global__ __launch_bounds__(256) void gemm_nt_bias(
    const float* __restrict__ A, const float* __restrict__ W,
    const float* __restrict__ bias, float* __restrict__ out,
    int M, int N, int K)
{
    __shared__ float As[16][64];
    __shared__ float Ws[16][64];
    const int n0 = blockIdx.x * 64;
    const int m0 = blockIdx.y * 64;
    const int tid = threadIdx.x;
    const int lr = tid >> 2;
    const int lk = (tid & 3) << 2;
    const int tx = tid & 15;
    const int ty = tid >> 4;

    unsigned long long acc[4][2];
#pragma unroll
    for (int i = 0; i < 4; i++) { acc[i][0] = 0ull; acc[i][1] = 0ull; }

    for (int k0 = 0; k0 < K; k0 += 16) {
        float4 a = *(const float4*)&A[(size_t)(m0 + lr) * K + k0 + lk];
        float4 w = *(const float4*)&W[(size_t)(n0 + lr) * K + k0 + lk];
        As[lk + 0][lr] = a.x; As[lk + 1][lr] = a.y; As[lk + 2][lr] = a.z; As[lk + 3][lr] = a.w;
        Ws[lk + 0][lr] = w.x; Ws[lk + 1][lr] = w.y; Ws[lk + 2][lr] = w.z; Ws[lk + 3][lr] = w.w;
        __syncthreads();
#pragma unroll
        for (int k = 0; k < 16; k++) {
            float4 av = *(const float4*)&As[k][ty * 4];
            ulonglong2 wv = *(const ulonglong2*)&Ws[k][tx * 4];
            unsigned long long a0 = dup2(av.x), a1 = dup2(av.y),
                               a2 = dup2(av.z), a3 = dup2(av.w);
            acc[0][0] = fma2(a0, wv.x, acc[0][0]); acc[0][1] = fma2(a0, wv.y, acc[0][1]);
            acc[1][0] = fma2(a1, wv.x, acc[1][0]); acc[1][1] = fma2(a1, wv.y, acc[1][1]);
            acc[2][0] = fma2(a2, wv.x, acc[2][0]); acc[2][1] = fma2(a2, wv.y, acc[2][1]);
            acc[3][0] = fma2(a3, wv.x, acc[3][0]); acc[3][1] = fma2(a3, wv.y, acc[3][1]);
        }
        __syncthreads();
    }
#pragma unroll
    for (int i = 0; i < 4; i++) {
        int m = m0 + ty * 4 + i;
        float c0, c1, c2, c3;
        unpack2(acc[i][0], c0, c1);
        unpack2(acc[i][1], c2, c3);
        int n = n0 + tx * 4;
        float4 o;
        o.x = c0 + bias[n + 0];
        o.y = c1 + bias[n + 1];
        o.z = c2 + bias[n + 2];
        o.w = c3 + bias[n + 3];
        *(float4*)&out[(size_t)m * N + n] = o;
    }
}

// -------- 8-CTA row-group barrier (single acq_rel atomic + acquire spin) --------
__device__ __forceinline__ void group_barrier(int g, unsigned target)
{
    __syncthreads();
    if (threadIdx.x == 0) {
        unsigned prev = atom_add_acqrel(&g_bar_count[g], 1u);
        if (prev == STRIPS - 1) {
            g_bar_count[g] = 0u;           // only leader writes; published by release below
            st_release(&g_bar_gen[g], target);
        } else {
            while (ld_acquire(&g_bar_gen[g]) < target) { }
        }
    }
    __syncthreads();
}

// -------- persistent GRU layer --------
// 128 CTAs = 16 rowtiles x 8 strips, 256 threads (8 warps = 2/SMSP).
// Warp pair (w, w+4): same 4 rows, K halves [0,128) / [128,256).
// Upper half stores 12 partials to smem; lower half combines + gates.
__global__ __launch_bounds__(256, 1) void gru_layer(
    const float* __restrict__ xp,   // [B*S, 768] x-proj incl. b_ih
    const float* __restrict__ Whh,  // [768, 256]
    const float* __restrict__ bhh,  // [768]
    float* __restrict__ h_seq,      // [B*S, 256] or null
    float* __restrict__ h_final)    // [B, 256] or null
{
    extern __shared__ float sm[];
    float* sW = sm;                       // [96][SW_STRIDE]
    float* sH = sm + W_FLOATS;            // [16][256]
    float* sRed = sm + W_FLOATS + H_FLOATS; // [16 rows][3 gates][32 lanes]

    const int cta = blockIdx.x;
    const int rowtile = cta >> 3;
    const int strip = cta & 7;
    const int j0 = strip * 32;
    const int r0 = rowtile * 16;
    const int tid = threadIdx.x;
    const int w = tid >> 5;
    const int l = tid & 31;
    const int wl = w & 3;                 // row quad
    const int half = w >> 2;              // K half
    const int khalf = half * 128;
    const int jj = j0 + l;

    // Preload W_hh strip (96 rows x 256) once.
    for (int i = tid; i < 96 * 64; i += 256) {
        int wrow = i >> 6;
        int k4 = (i & 63) << 2;
        int g = wrow >> 5, jc = wrow & 31;
        float4 v = *(const float4*)&Whh[(size_t)(g * H + j0 + jc) * H + k4];
        *(float4*)&sW[wrow * SW_STRIDE + k4] = v;
    }
    const float bhr = bhh[jj];
    const float bhz = bhh[H + jj];
    const float bhn = bhh[2 * H + jj];

    // zero h0 slice (16 rows x own 32 cols)
    for (int i = tid; i < 16 * 32; i += 256) {
        int rr = i >> 5, cc = i & 31;
        g_hbuf[(size_t)(r0 + rr) * H + j0 + cc] = 0.f;
    }

    unsigned target = *((volatile unsigned*)&g_bar_gen[rowtile]);
    target++;
    group_barrier(rowtile, target);

    const float* wrp = sW + l * SW_STRIDE + khalf;
    const float* wzp = sW + (32 + l) * SW_STRIDE + khalf;
    const float* wnp = sW + (64 + l) * SW_STRIDE + khalf;

    for (int t = 0; t < S; t++) {
        const float* hcur = g_hbuf + (size_t)(t & 1) * (B * H);
        float* hnext = g_hbuf + (size_t)((t + 1) & 1) * (B * H);

        // xp prefetch (lower-half warps only; consumed at gating)
        float pxr[4], pxz[4], pxn[4];
        if (half == 0) {
#pragma unroll
            for (int i = 0; i < 4; i++) {
                size_t xb = ((size_t)(r0 + wl * 4 + i) * S + t) * G3 + jj;
                pxr[i] = __ldg(&xp[xb]);
                pxz[i] = __ldg(&xp[xb + H]);
                pxn[i] = __ldg(&xp[xb + 2 * H]);
            }
        }

        // stage h tile (16 x 256) via L2
        for (int i = tid; i < 16 * 64; i += 256) {
            int rr = i >> 6, k4 = (i & 63) << 2;
            float4 v = __ldcg((const float4*)&hcur[(size_t)(r0 + rr) * H + k4]);
            *(float4*)&sH[rr * SH_STRIDE + k4] = v;
        }
        __syncthreads();

        unsigned long long ar2[4], az2[4], an2[4];
#pragma unroll
        for (int i = 0; i < 4; i++) { ar2[i] = 0ull; az2[i] = 0ull; an2[i] = 0ull; }

        const float* hb = sH + wl * 4 * SH_STRIDE + khalf;

#pragma unroll 8
        for (int k = 0; k < 128; k += 4) {
            ulonglong2 wrv = *(const ulonglong2*)(wrp + k);
            ulonglong2 wzv = *(const ulonglong2*)(wzp + k);
            ulonglong2 wnv = *(const ulonglong2*)(wnp + k);
#pragma unroll
            for (int i = 0; i < 4; i++) {
                ulonglong2 hv = *(const ulonglong2*)(hb + i * SH_STRIDE + k); // broadcast
                ar2[i] = fma2(hv.x, wrv.x, ar2[i]);
                az2[i] = fma2(hv.x, wzv.x, az2[i]);
                an2[i] = fma2(hv.x, wnv.x, an2[i]);
                ar2[i] = fma2(hv.y, wrv.y, ar2[i]);
                az2[i] = fma2(hv.y, wzv.y, az2[i]);
                an2[i] = fma2(hv.y, wnv.y, an2[i]);
            }
        }

        // upper half publishes partials
        if (half == 1) {
#pragma unroll
            for (int i = 0; i < 4; i++) {
                int rbase = (wl * 4 + i) * 3;
                sRed[(rbase + 0) * 32 + l] = hsum2(ar2[i]);
                sRed[(rbase + 1) * 32 + l] = hsum2(az2[i]);
                sRed[(rbase + 2) * 32 + l] = hsum2(an2[i]);
            }
        }
        __syncthreads();

        if (half == 0) {
#pragma unroll
            for (int i = 0; i < 4; i++) {
                int rloc = wl * 4 + i;
                int row = r0 + rloc;
                int rbase = rloc * 3;
                float sr = hsum2(ar2[i]) + sRed[(rbase + 0) * 32 + l];
                float sz = hsum2(az2[i]) + sRed[(rbase + 1) * 32 + l];
                float sn = hsum2(an2[i]) + sRed[(rbase + 2) * 32 + l];
                float rg = sigmoid_ap(pxr[i] + sr + bhr);
                float zg = sigmoid_ap(pxz[i] + sz + bhz);
                float ng = tanh_ap(pxn[i] + rg * (sn + bhn));
                float hold = sH[rloc * SH_STRIDE + jj];
                float hnew = (1.f - zg) * ng + zg * hold;
                hnext[(size_t)row * H + jj] = hnew;
                if (h_seq) h_seq[((size_t)row * S + t) * H + jj] = hnew;
                if (h_final && t == S - 1) h_final[(size_t)row * H + jj] = hnew;
            }
        }

        target++;
        group_barrier(rowtile, target);
    }
}

// -------- projection + 96-step diagonal forecast, fused --------
__global__ void forecast_kernel(
    const float* __restrict__ h2, const float* __restrict__ Wp,
    const float* __restrict__ bp, const float* __restrict__ C,
    const float* __restrict__ rld, const float* __restrict__ rtd,
    const float* __restrict__ rg_, const float* __restrict__ om,
    float* __restrict__ out)
{
    const int b = blockIdx.x;
    const int d = threadIdx.x;
    __shared__ float sh[H];
    for (int i = d; i < H; i += 32) sh[i] = h2[(size_t)b * H + i];
    __syncthreads();

    float s[NSTATE];
#pragma unroll
    for (int st = 0; st < NSTATE; st++) {
        const float* w = Wp + (size_t)(d * NSTATE + st) * H;
        float acc = bp[d * NSTATE + st];
        for (int k = 0; k < H; k += 4) {
            float4 wv = *(const float4*)(w + k);
            acc += sh[k] * wv.x + sh[k + 1] * wv.y + sh[k + 2] * wv.z + sh[k + 3] * wv.w;
        }
        s[st] = acc;
    }

    float al = 1.f / (1.f + expf(-rld[d])) * 0.15f + 0.85f;
    float at = 1.f / (1.f + expf(-rtd[d])) * 0.25f + 0.70f;
    float gg = 1.f / (1.f + expf(-rg_[d])) * 0.20f + 0.80f;
    float cc = cosf(om[d]), sn = sinf(om[d]);
    float r00 = gg * cc, r01 = -gg * sn, r10 = gg * sn, r11 = gg * cc;
    float C0 = C[d * 4 + 0], C1 = C[d * 4 + 1], C2 = C[d * 4 + 2], C3 = C[d * 4 + 3];

    for (int p = 0; p < PRED; p++) {
        float n0 = s[0] * al;
        float n1 = s[1] * at;
        float n2 = s[2] * r00 + s[3] * r10;
        float n3 = s[2] * r01 + s[3] * r11;
        s[0] = n0; s[1] = n1; s[2] = n2; s[3] = n3;
        out[((size_t)b * PRED + p) * D_OUT + d] = C0 * n0 + C1 * n1 + C2 * n2 + C3 * n3;
    }
}

extern "C" void kernel_launch(void* const* d_in, const int* in_sizes, int n_in,
                              void* d_out, int out_size)
{
    const float* x    = (const float*)d_in[0];
    const float* Wih0 = (const float*)d_in[1];
    const float* Whh0 = (const float*)d_in[2];
    const float* bih0 = (const float*)d_in[3];
    const float* bhh0 = (const float*)d_in[4];
    const float* Wih1 = (const float*)d_in[5];
    const float* Whh1 = (const float*)d_in[6];
    const float* bih1 = (const float*)d_in[7];
    const float* bhh1 = (const float*)d_in[8];
    const float* Wp   = (const float*)d_in[9];
    const float* bp   = (const float*)d_in[10];
    const float* C    = (const float*)d_in[11];
    const float* rld  = (const float*)d_in[12];
    const float* rtd  = (const float*)d_in[13];
    const float* rg   = (const float*)d_in[14];
    const float* om   = (const float*)d_in[15];
    float* out = (float*)d_out;

    float *xp, *h1s, *h2;
    cudaGetSymbolAddress((void**)&xp, g_xp);
    cudaGetSymbolAddress((void**)&h1s, g_h1s);
    cudaGetSymbolAddress((void**)&h2, g_h2);

    cudaFuncSetAttribute(gru_layer, cudaFuncAttributeMaxDynamicSharedMemorySize, SMEM_BYTES);

    dim3 gg(G3 / 64, (B * S) / 64);

    gemm_nt_bias<<<gg, 256>>>(x, Wih0, bih0, xp, B * S, G3, IN_F);
    gru_layer<<<GRU_CTAS, 256, SMEM_BYTES>>>(xp, Whh0, bhh0, h1s, nullptr);
    gemm_nt_bias<<<gg, 256>>>(h1s, Wih1, bih1, xp, B * S, G3, H);
    gru_layer<<<GRU_CTAS, 256, SMEM_BYTES>>>(xp, Whh1, bhh1, nullptr, h2);
    forecast_kernel<<<B, 32>>>(h2, Wp, bp, C, rld, rtd, rg, om, out);
}

// round 6
// speedup vs baseline: 1.2541x; 1.0870x over previous
#include <cuda_runtime.h>
#include <cstdint>

#define B 256
#define S 512
#define IN_F 32
#define H 256
#define G3 768
#define D_OUT 32
#define NSTATE 4
#define PRED 96

#define GRU_CTAS 128
#define ROWTILES 16
#define STRIPS 8
#define SW_STRIDE 260          // % 32 == 4 -> conflict-free LDS.128 per 8-lane phase
#define SH_STRIDE 256
#define W_FLOATS (96 * SW_STRIDE)      // 24960
#define H_FLOATS (16 * SH_STRIDE)      // 4096
#define SMEM_FLOATS (W_FLOATS + H_FLOATS)
#define SMEM_BYTES (SMEM_FLOATS * 4)   // 116224 B

#define FLAG_STRIDE 32                 // 1 flag per 128B line

// -------- packed f32x2 helpers --------
__device__ __forceinline__ unsigned long long fma2(unsigned long long a,
                                                   unsigned long long b,
                                                   unsigned long long c)
{
    unsigned long long d;
    asm("fma.rn.f32x2 %0, %1, %2, %3;" : "=l"(d) : "l"(a), "l"(b), "l"(c));
    return d;
}
__device__ __forceinline__ unsigned long long dup2(float x)
{
    unsigned long long d;
    unsigned r = __float_as_uint(x);
    asm("mov.b64 %0, {%1, %1};" : "=l"(d) : "r"(r));
    return d;
}
__device__ __forceinline__ float hsum2(unsigned long long a)
{
    unsigned lo, hi;
    asm("mov.b64 {%0, %1}, %2;" : "=r"(lo), "=r"(hi) : "l"(a));
    return __uint_as_float(lo) + __uint_as_float(hi);
}
__device__ __forceinline__ void unpack2(unsigned long long a, float& lo, float& hi)
{
    unsigned l, h;
    asm("mov.b64 {%0, %1}, %2;" : "=r"(l), "=r"(h) : "l"(a));
    lo = __uint_as_float(l); hi = __uint_as_float(h);
}
__device__ __forceinline__ float tanh_ap(float x)
{
    float y;
    asm("tanh.approx.f32 %0, %1;" : "=f"(y) : "f"(x));
    return y;
}
__device__ __forceinline__ float sigmoid_ap(float x)
{
    return 0.5f * tanh_ap(0.5f * x) + 0.5f;
}

// -------- release/acquire primitives --------
__device__ __forceinline__ void st_release(unsigned* p, unsigned v)
{
    asm volatile("st.release.gpu.global.u32 [%0], %1;" :: "l"(p), "r"(v) : "memory");
}
__device__ __forceinline__ unsigned ld_acquire(const unsigned* p)
{
    unsigned v;
    asm volatile("ld.acquire.gpu.global.u32 %0, [%1];" : "=r"(v) : "l"(p) : "memory");
    return v;
}

// -------- scratch --------
__device__ float g_xp[(size_t)B * S * G3];
__device__ float g_h1s[(size_t)B * S * H];
__device__ float g_hbuf[2 * B * H];
__device__ float g_h2[B * H];
__device__ unsigned g_flags[ROWTILES * STRIPS * FLAG_STRIDE];   // padded: 1 per 128B line

// -------- SGEMM (R2-proven 64x64 tile): out[M,N] = A[M,K] @ W[N,K]^T + bias --------
__global__ __launch_bounds__(256) void gemm_nt_bias(
    const float* __restrict__ A, const float* __restrict__ W,
    const float* __restrict__ bias, float* __restrict__ out,
    int M, int N, int K)
{
    __shared__ float As[16][64];
    __shared__ float Ws[16][64];
    const int n0 = blockIdx.x * 64;
    const int m0 = blockIdx.y * 64;
    const int tid = threadIdx.x;
    const int lr = tid >> 2;
    const int lk = (tid & 3) << 2;
    const int tx = tid & 15;
    const int ty = tid >> 4;

    unsigned long long acc[4][2];
#pragma unroll
    for (int i = 0; i < 4; i++) { acc[i][0] = 0ull; acc[i][1] = 0ull; }

    for (int k0 = 0; k0 < K; k0 += 16) {
        float4 a = *(const float4*)&A[(size_t)(m0 + lr) * K + k0 + lk];
        float4 w = *(const float4*)&W[(size_t)(n0 + lr) * K + k0 + lk];
        As[lk + 0][lr] = a.x; As[lk + 1][lr] = a.y; As[lk + 2][lr] = a.z; As[lk + 3][lr] = a.w;
        Ws[lk + 0][lr] = w.x; Ws[lk + 1][lr] = w.y; Ws[lk + 2][lr] = w.z; Ws[lk + 3][lr] = w.w;
        __syncthreads();
#pragma unroll
        for (int k = 0; k < 16; k++) {
            float4 av = *(const float4*)&As[k][ty * 4];
            ulonglong2 wv = *(const ulonglong2*)&Ws[k][tx * 4];
            unsigned long long a0 = dup2(av.x), a1 = dup2(av.y),
                               a2 = dup2(av.z), a3 = dup2(av.w);
            acc[0][0] = fma2(a0, wv.x, acc[0][0]); acc[0][1] = fma2(a0, wv.y, acc[0][1]);
            acc[1][0] = fma2(a1, wv.x, acc[1][0]); acc[1][1] = fma2(a1, wv.y, acc[1][1]);
            acc[2][0] = fma2(a2, wv.x, acc[2][0]); acc[2][1] = fma2(a2, wv.y, acc[2][1]);
            acc[3][0] = fma2(a3, wv.x, acc[3][0]); acc[3][1] = fma2(a3, wv.y, acc[3][1]);
        }
        __syncthreads();
    }
#pragma unroll
    for (int i = 0; i < 4; i++) {
        int m = m0 + ty * 4 + i;
        float c0, c1, c2, c3;
        unpack2(acc[i][0], c0, c1);
        unpack2(acc[i][1], c2, c3);
        int n = n0 + tx * 4;
        float4 o;
        o.x = c0 + bias[n + 0];
        o.y = c1 + bias[n + 1];
        o.z = c2 + bias[n + 2];
        o.w = c3 + bias[n + 3];
        *(float4*)&out[(size_t)m * N + n] = o;
    }
}

// -------- distributed padded flag barrier (8 strips of one rowtile) --------
// Arrive: release-store own flag = target. Wait: lanes 0..7 acquire-spin on
// one strip's flag each (8-way MLP, plain loads, no atomics, no shared lines).
__device__ __forceinline__ void strip_barrier(int rowtile, int strip, unsigned target)
{
    __threadfence();
    __syncthreads();
    if (threadIdx.x == 0)
        st_release(&g_flags[(rowtile * STRIPS + strip) * FLAG_STRIDE], target);
    if (threadIdx.x < STRIPS) {
        const unsigned* f = &g_flags[(rowtile * STRIPS + threadIdx.x) * FLAG_STRIDE];
        while (ld_acquire(f) < target) { }
    }
    __syncthreads();
}

// -------- persistent GRU layer (R2 core + new barrier) --------
__global__ __launch_bounds__(128, 1) void gru_layer(
    const float* __restrict__ xp,   // [B*S, 768] x-proj incl. b_ih
    const float* __restrict__ Whh,  // [768, 256]
    const float* __restrict__ bhh,  // [768]
    float* __restrict__ h_seq,      // [B*S, 256] or null
    float* __restrict__ h_final)    // [B, 256] or null
{
    extern __shared__ float sm[];
    float* sW = sm;                       // [96][SW_STRIDE]
    float* sH = sm + W_FLOATS;            // [16][256]

    const int cta = blockIdx.x;
    const int rowtile = cta >> 3;
    const int strip = cta & 7;
    const int j0 = strip * 32;
    const int r0 = rowtile * 16;
    const int tid = threadIdx.x;
    const int j = tid & 31;
    const int rq = tid >> 5;   // warp id: owns rows r0+rq*4 .. +3
    const int jj = j0 + j;

    // Preload W_hh strips (gate g, cols j0..j0+31) once.
    for (int i = tid; i < 96 * 64; i += 128) {
        int wrow = i >> 6;            // g*32 + jc
        int k4 = (i & 63) << 2;
        int g = wrow >> 5, jc = wrow & 31;
        float4 v = *(const float4*)&Whh[(size_t)(g * H + j0 + jc) * H + k4];
        *(float4*)&sW[wrow * SW_STRIDE + k4] = v;
    }
    const float bhr = bhh[jj];
    const float bhz = bhh[H + jj];
    const float bhn = bhh[2 * H + jj];

#pragma unroll
    for (int i = 0; i < 4; i++) {
        int row = r0 + rq * 4 + i;
        g_hbuf[(size_t)row * H + jj] = 0.f;
    }

    // Monotonic barrier target (flags persist across launches/replays).
    unsigned target =
        *((volatile unsigned*)&g_flags[(rowtile * STRIPS + strip) * FLAG_STRIDE]);
    target++;
    strip_barrier(rowtile, strip, target);   // zeros + smem W visible

    const float* wr = sW + j * SW_STRIDE;
    const float* wz = sW + (32 + j) * SW_STRIDE;
    const float* wn = sW + (64 + j) * SW_STRIDE;

    for (int t = 0; t < S; t++) {
        const float* hcur = g_hbuf + (size_t)(t & 1) * (B * H);
        float* hnext = g_hbuf + (size_t)((t + 1) & 1) * (B * H);

        // Prefetch this step's xp values FIRST (independent of h).
        float pxr[4], pxz[4], pxn[4];
#pragma unroll
        for (int i = 0; i < 4; i++) {
            size_t xb = ((size_t)(r0 + rq * 4 + i) * S + t) * G3 + jj;
            pxr[i] = __ldg(&xp[xb]);
            pxz[i] = __ldg(&xp[xb + H]);
            pxn[i] = __ldg(&xp[xb + 2 * H]);
        }

        // Stage this tile's 16 h rows (L2-coherent: peers wrote them).
        for (int i = tid; i < 16 * 64; i += 128) {
            int rr = i >> 6, k4 = (i & 63) << 2;
            float4 v = __ldcg((const float4*)&hcur[(size_t)(r0 + rr) * H + k4]);
            *(float4*)&sH[rr * SH_STRIDE + k4] = v;
        }
        __syncthreads();

        unsigned long long ar2[4], az2[4], an2[4];
#pragma unroll
        for (int i = 0; i < 4; i++) { ar2[i] = 0ull; az2[i] = 0ull; an2[i] = 0ull; }

        const float* hb = sH + rq * 4 * SH_STRIDE;

#pragma unroll 8
        for (int k = 0; k < H; k += 4) {
            ulonglong2 wrv = *(const ulonglong2*)(wr + k);
            ulonglong2 wzv = *(const ulonglong2*)(wz + k);
            ulonglong2 wnv = *(const ulonglong2*)(wn + k);
#pragma unroll
            for (int i = 0; i < 4; i++) {
                ulonglong2 hv = *(const ulonglong2*)(hb + i * SH_STRIDE + k);  // broadcast
                ar2[i] = fma2(hv.x, wrv.x, ar2[i]);
                az2[i] = fma2(hv.x, wzv.x, az2[i]);
                an2[i] = fma2(hv.x, wnv.x, an2[i]);
                ar2[i] = fma2(hv.y, wrv.y, ar2[i]);
                az2[i] = fma2(hv.y, wzv.y, az2[i]);
                an2[i] = fma2(hv.y, wnv.y, an2[i]);
            }
        }

#pragma unroll
        for (int i = 0; i < 4; i++) {
            int rloc = rq * 4 + i;
            int row = r0 + rloc;
            float rg = sigmoid_ap(pxr[i] + hsum2(ar2[i]) + bhr);
            float zg = sigmoid_ap(pxz[i] + hsum2(az2[i]) + bhz);
            float ng = tanh_ap(pxn[i] + rg * (hsum2(an2[i]) + bhn));
            float hold = sH[rloc * SH_STRIDE + jj];
            float hnew = (1.f - zg) * ng + zg * hold;
            hnext[(size_t)row * H + jj] = hnew;
            if (h_seq) h_seq[((size_t)row * S + t) * H + jj] = hnew;
            if (h_final && t == S - 1) h_final[(size_t)row * H + jj] = hnew;
        }

        target++;
        strip_barrier(rowtile, strip, target);
    }
}

// -------- projection + 96-step diagonal forecast, fused --------
__global__ void forecast_kernel(
    const float* __restrict__ h2, const float* __restrict__ Wp,
    const float* __restrict__ bp, const float* __restrict__ C,
    const float* __restrict__ rld, const float* __restrict__ rtd,
    const float* __restrict__ rg_, const float* __restrict__ om,
    float* __restrict__ out)
{
    const int b = blockIdx.x;
    const int d = threadIdx.x;
    __shared__ float sh[H];
    for (int i = d; i < H; i += 32) sh[i] = h2[(size_t)b * H + i];
    __syncthreads();

    float s[NSTATE];
#pragma unroll
    for (int st = 0; st < NSTATE; st++) {
        const float* w = Wp + (size_t)(d * NSTATE + st) * H;
        float acc = bp[d * NSTATE + st];
        for (int k = 0; k < H; k += 4) {
            float4 wv = *(const float4*)(w + k);
            acc += sh[k] * wv.x + sh[k + 1] * wv.y + sh[k + 2] * wv.z + sh[k + 3] * wv.w;
        }
        s[st] = acc;
    }

    float al = 1.f / (1.f + expf(-rld[d])) * 0.15f + 0.85f;
    float at = 1.f / (1.f + expf(-rtd[d])) * 0.25f + 0.70f;
    float gg = 1.f / (1.f + expf(-rg_[d])) * 0.20f + 0.80f;
    float cc = cosf(om[d]), sn = sinf(om[d]);
    float r00 = gg * cc, r01 = -gg * sn, r10 = gg * sn, r11 = gg * cc;
    float C0 = C[d * 4 + 0], C1 = C[d * 4 + 1], C2 = C[d * 4 + 2], C3 = C[d * 4 + 3];

    for (int p = 0; p < PRED; p++) {
        float n0 = s[0] * al;
        float n1 = s[1] * at;
        float n2 = s[2] * r00 + s[3] * r10;
        float n3 = s[2] * r01 + s[3] * r11;
        s[0] = n0; s[1] = n1; s[2] = n2; s[3] = n3;
        out[((size_t)b * PRED + p) * D_OUT + d] = C0 * n0 + C1 * n1 + C2 * n2 + C3 * n3;
    }
}

extern "C" void kernel_launch(void* const* d_in, const int* in_sizes, int n_in,
                              void* d_out, int out_size)
{
    const float* x    = (const float*)d_in[0];
    const float* Wih0 = (const float*)d_in[1];
    const float* Whh0 = (const float*)d_in[2];
    const float* bih0 = (const float*)d_in[3];
    const float* bhh0 = (const float*)d_in[4];
    const float* Wih1 = (const float*)d_in[5];
    const float* Whh1 = (const float*)d_in[6];
    const float* bih1 = (const float*)d_in[7];
    const float* bhh1 = (const float*)d_in[8];
    const float* Wp   = (const float*)d_in[9];
    const float* bp   = (const float*)d_in[10];
    const float* C    = (const float*)d_in[11];
    const float* rld  = (const float*)d_in[12];
    const float* rtd  = (const float*)d_in[13];
    const float* rg   = (const float*)d_in[14];
    const float* om   = (const float*)d_in[15];
    float* out = (float*)d_out;

    float *xp, *h1s, *h2;
    cudaGetSymbolAddress((void**)&xp, g_xp);
    cudaGetSymbolAddress((void**)&h1s, g_h1s);
    cudaGetSymbolAddress((void**)&h2, g_h2);

    cudaFuncSetAttribute(gru_layer, cudaFuncAttributeMaxDynamicSharedMemorySize, SMEM_BYTES);

    dim3 gg(G3 / 64, (B * S) / 64);

    gemm_nt_bias<<<gg, 256>>>(x, Wih0, bih0, xp, B * S, G3, IN_F);
    gru_layer<<<GRU_CTAS, 128, SMEM_BYTES>>>(xp, Whh0, bhh0, h1s, nullptr);
    gemm_nt_bias<<<gg, 256>>>(h1s, Wih1, bih1, xp, B * S, G3, H);
    gru_layer<<<GRU_CTAS, 128, SMEM_BYTES>>>(xp, Whh1, bhh1, nullptr, h2);
    forecast_kernel<<<B, 32>>>(h2, Wp, bp, C, rld, rtd, rg, om, out);
}

// round 7
// speedup vs baseline: 1.3984x; 1.1151x over previous
#include <cuda_runtime.h>
#include <cstdint>

#define B 256
#define S 512
#define IN_F 32
#define H 256
#define G3 768
#define D_OUT 32
#define NSTATE 4
#define PRED 96

#define GRU_CTAS 128
#define ROWTILES 16
#define STRIPS 8
#define SW_STRIDE 260          // % 32 == 4 -> conflict-free LDS.128 per 8-lane phase
#define SH_STRIDE 256
#define W_FLOATS (96 * SW_STRIDE)      // 24960
#define H_FLOATS (16 * SH_STRIDE)      // 4096
#define SMEM_FLOATS (W_FLOATS + H_FLOATS)
#define SMEM_BYTES (SMEM_FLOATS * 4)   // 116224 B

#define FLAG_STRIDE 32                 // 1 flag per 128B line

// -------- packed f32x2 helpers --------
__device__ __forceinline__ unsigned long long fma2(unsigned long long a,
                                                   unsigned long long b,
                                                   unsigned long long c)
{
    unsigned long long d;
    asm("fma.rn.f32x2 %0, %1, %2, %3;" : "=l"(d) : "l"(a), "l"(b), "l"(c));
    return d;
}
__device__ __forceinline__ unsigned long long dup2(float x)
{
    unsigned long long d;
    unsigned r = __float_as_uint(x);
    asm("mov.b64 %0, {%1, %1};" : "=l"(d) : "r"(r));
    return d;
}
__device__ __forceinline__ float hsum2(unsigned long long a)
{
    unsigned lo, hi;
    asm("mov.b64 {%0, %1}, %2;" : "=r"(lo), "=r"(hi) : "l"(a));
    return __uint_as_float(lo) + __uint_as_float(hi);
}
__device__ __forceinline__ void unpack2(unsigned long long a, float& lo, float& hi)
{
    unsigned l, h;
    asm("mov.b64 {%0, %1}, %2;" : "=r"(l), "=r"(h) : "l"(a));
    lo = __uint_as_float(l); hi = __uint_as_float(h);
}
__device__ __forceinline__ float tanh_ap(float x)
{
    float y;
    asm("tanh.approx.f32 %0, %1;" : "=f"(y) : "f"(x));
    return y;
}
__device__ __forceinline__ float sigmoid_ap(float x)
{
    return 0.5f * tanh_ap(0.5f * x) + 0.5f;
}

// -------- release/acquire primitives --------
__device__ __forceinline__ void red_release_add(unsigned* p, unsigned v)
{
    asm volatile("red.release.gpu.global.add.u32 [%0], %1;" :: "l"(p), "r"(v) : "memory");
}
__device__ __forceinline__ unsigned ld_acquire(const unsigned* p)
{
    unsigned v;
    asm volatile("ld.acquire.gpu.global.u32 %0, [%1];" : "=r"(v) : "l"(p) : "memory");
    return v;
}

// -------- scratch --------
__device__ float g_xp[(size_t)B * S * G3];
__device__ float g_h1s[(size_t)B * S * H];
__device__ float g_hbuf[2 * B * H];
__device__ float g_h2[B * H];
__device__ unsigned g_flags[ROWTILES * STRIPS * FLAG_STRIDE];   // 1 per 128B line

// -------- SGEMM: out[M,N] = A[M,K] @ W[N,K]^T + bias[N] --------
// Tile 128(M) x 64(N), 256 threads, 8x4 micro-tile, packed f32x2.
__global__ __launch_bounds__(256) void gemm_nt_bias(
    const float* __restrict__ A, const float* __restrict__ W,
    const float* __restrict__ bias, float* __restrict__ out,
    int M, int N, int K)
{
    __shared__ float As[16 * 128];   // [k][m]
    __shared__ float Ws[16 * 64];    // [k][n]
    const int n0 = blockIdx.x * 64;
    const int m0 = blockIdx.y * 128;
    const int tid = threadIdx.x;
    const int tx = tid & 15;
    const int ty = tid >> 4;
    const int war = tid & 63;
    const int wak = (tid >> 6) << 2;

    unsigned long long acc[8][2];
#pragma unroll
    for (int i = 0; i < 8; i++) { acc[i][0] = 0ull; acc[i][1] = 0ull; }

    for (int k0 = 0; k0 < K; k0 += 16) {
#pragma unroll
        for (int r = 0; r < 2; r++) {
            int f4id = r * 256 + tid;
            int ar = f4id & 127;
            int ak = (f4id >> 7) << 2;
            float4 a = *(const float4*)&A[(size_t)(m0 + ar) * K + k0 + ak];
            As[(ak + 0) * 128 + ar] = a.x;
            As[(ak + 1) * 128 + ar] = a.y;
            As[(ak + 2) * 128 + ar] = a.z;
            As[(ak + 3) * 128 + ar] = a.w;
        }
        {
            float4 w = *(const float4*)&W[(size_t)(n0 + war) * K + k0 + wak];
            Ws[(wak + 0) * 64 + war] = w.x;
            Ws[(wak + 1) * 64 + war] = w.y;
            Ws[(wak + 2) * 64 + war] = w.z;
            Ws[(wak + 3) * 64 + war] = w.w;
        }
        __syncthreads();
#pragma unroll
        for (int k = 0; k < 16; k++) {
            float4 av0 = *(const float4*)&As[k * 128 + ty * 8];
            float4 av1 = *(const float4*)&As[k * 128 + ty * 8 + 4];
            ulonglong2 wv = *(const ulonglong2*)&Ws[k * 64 + tx * 4];
            float am[8] = {av0.x, av0.y, av0.z, av0.w, av1.x, av1.y, av1.z, av1.w};
#pragma unroll
            for (int i = 0; i < 8; i++) {
                unsigned long long ai = dup2(am[i]);
                acc[i][0] = fma2(ai, wv.x, acc[i][0]);
                acc[i][1] = fma2(ai, wv.y, acc[i][1]);
            }
        }
        __syncthreads();
    }

    float4 bv = *(const float4*)&bias[n0 + tx * 4];
#pragma unroll
    for (int i = 0; i < 8; i++) {
        int m = m0 + ty * 8 + i;
        float c0, c1, c2, c3;
        unpack2(acc[i][0], c0, c1);
        unpack2(acc[i][1], c2, c3);
        float4 o;
        o.x = c0 + bv.x; o.y = c1 + bv.y; o.z = c2 + bv.z; o.w = c3 + bv.w;
        *(float4*)&out[(size_t)m * N + n0 + tx * 4] = o;
    }
}

// -------- persistent GRU layer --------
// 128 CTAs = 16 rowtiles x 8 strips, 128 threads.
// Arrival: every thread red.release-adds 1 to its strip's padded flag
// (orders that thread's h stores). Wait: lanes 0..7 acquire-poll one strip
// flag each for base + 128*(t+1). Layer 0 uses h_seq itself as the exchange
// buffer (step-unique addresses); layer 1 double-buffers in g_hbuf.
__global__ __launch_bounds__(128, 1) void gru_layer(
    const float* __restrict__ xp,   // [B*S, 768] x-proj incl. b_ih
    const float* __restrict__ Whh,  // [768, 256]
    const float* __restrict__ bhh,  // [768]
    float* __restrict__ h_seq,      // [B*S, 256] or null
    float* __restrict__ h_final)    // [B, 256] or null
{
    extern __shared__ float sm[];
    float* sW = sm;                       // [96][SW_STRIDE]
    float* sH = sm + W_FLOATS;            // [16][256]

    const int cta = blockIdx.x;
    const int rowtile = cta >> 3;
    const int strip = cta & 7;
    const int j0 = strip * 32;
    const int r0 = rowtile * 16;
    const int tid = threadIdx.x;
    const int j = tid & 31;
    const int rq = tid >> 5;   // warp id: owns rows r0+rq*4 .. +3
    const int jj = j0 + j;

    // Preload W_hh strips (gate g, cols j0..j0+31) once.
    for (int i = tid; i < 96 * 64; i += 128) {
        int wrow = i >> 6;            // g*32 + jc
        int k4 = (i & 63) << 2;
        int g = wrow >> 5, jc = wrow & 31;
        float4 v = *(const float4*)&Whh[(size_t)(g * H + j0 + jc) * H + k4];
        *(float4*)&sW[wrow * SW_STRIDE + k4] = v;
    }
    const float bhr = bhh[jj];
    const float bhz = bhh[H + jj];
    const float bhn = bhh[2 * H + jj];

    // Stage h(-1) = 0 locally; no gmem zeroing, no initial barrier.
    for (int i = tid; i < H_FLOATS; i += 128) sH[i] = 0.f;

    unsigned* ownFlag = &g_flags[(rowtile * STRIPS + strip) * FLAG_STRIDE];
    const unsigned base = *((volatile unsigned*)ownFlag);

    // Prefetch xp for t=0.
    float pxr[4], pxz[4], pxn[4];
#pragma unroll
    for (int i = 0; i < 4; i++) {
        size_t xb = ((size_t)(r0 + rq * 4 + i) * S + 0) * G3 + jj;
        pxr[i] = __ldg(&xp[xb]);
        pxz[i] = __ldg(&xp[xb + H]);
        pxn[i] = __ldg(&xp[xb + 2 * H]);
    }
    __syncthreads();   // sH zeros + sW visible

    const float* wr = sW + j * SW_STRIDE;
    const float* wz = sW + (32 + j) * SW_STRIDE;
    const float* wn = sW + (64 + j) * SW_STRIDE;

    for (int t = 0; t < S; t++) {
        // ---- dot product from sH (h(t-1)) ----
        unsigned long long ar2[4], az2[4], an2[4];
#pragma unroll
        for (int i = 0; i < 4; i++) { ar2[i] = 0ull; az2[i] = 0ull; an2[i] = 0ull; }

        const float* hb = sH + rq * 4 * SH_STRIDE;

#pragma unroll 8
        for (int k = 0; k < H; k += 4) {
            ulonglong2 wrv = *(const ulonglong2*)(wr + k);
            ulonglong2 wzv = *(const ulonglong2*)(wz + k);
            ulonglong2 wnv = *(const ulonglong2*)(wn + k);
#pragma unroll
            for (int i = 0; i < 4; i++) {
                ulonglong2 hv = *(const ulonglong2*)(hb + i * SH_STRIDE + k);  // broadcast
                ar2[i] = fma2(hv.x, wrv.x, ar2[i]);
                az2[i] = fma2(hv.x, wzv.x, az2[i]);
                an2[i] = fma2(hv.x, wnv.x, an2[i]);
                ar2[i] = fma2(hv.y, wrv.y, ar2[i]);
                az2[i] = fma2(hv.y, wzv.y, az2[i]);
                an2[i] = fma2(hv.y, wnv.y, an2[i]);
            }
        }

        // ---- gating + h store ----
#pragma unroll
        for (int i = 0; i < 4; i++) {
            int rloc = rq * 4 + i;
            int row = r0 + rloc;
            float rg = sigmoid_ap(pxr[i] + hsum2(ar2[i]) + bhr);
            float zg = sigmoid_ap(pxz[i] + hsum2(az2[i]) + bhz);
            float ng = tanh_ap(pxn[i] + rg * (hsum2(an2[i]) + bhn));
            float hold = sH[rloc * SH_STRIDE + jj];
            float hnew = (1.f - zg) * ng + zg * hold;
            if (h_seq) {
                h_seq[((size_t)row * S + t) * H + jj] = hnew;   // layer 0: single store
            } else {
                g_hbuf[(size_t)(((t + 1) & 1) * B + row) * H + jj] = hnew;
                if (h_final && t == S - 1) h_final[(size_t)row * H + jj] = hnew;
            }
        }

        if (t + 1 < S) {
            // arrive: release-red orders this thread's h stores before the add
            red_release_add(ownFlag, 1u);

            // prefetch xp for t+1 while peers finish (hidden in wait window)
#pragma unroll
            for (int i = 0; i < 4; i++) {
                size_t xb = ((size_t)(r0 + rq * 4 + i) * S + (t + 1)) * G3 + jj;
                pxr[i] = __ldg(&xp[xb]);
                pxz[i] = __ldg(&xp[xb + H]);
                pxn[i] = __ldg(&xp[xb + 2 * H]);
            }

            // wait: all 8 strips' flags must reach base + 128*(t+1)
            unsigned tgt = base + (unsigned)(t + 1) * 128u;
            if (tid < STRIPS) {
                const unsigned* f = &g_flags[(rowtile * STRIPS + tid) * FLAG_STRIDE];
                while ((int)(ld_acquire(f) - tgt) < 0) { }
            }
            __syncthreads();

            // stage h(t) for next step
            if (h_seq) {
                for (int i = tid; i < 16 * 64; i += 128) {
                    int rr = i >> 6, k4 = (i & 63) << 2;
                    float4 v = __ldcg((const float4*)
                        &h_seq[((size_t)(r0 + rr) * S + t) * H + k4]);
                    *(float4*)&sH[rr * SH_STRIDE + k4] = v;
                }
            } else {
                const float* hsrc = g_hbuf + (size_t)(((t + 1) & 1) * B) * H;
                for (int i = tid; i < 16 * 64; i += 128) {
                    int rr = i >> 6, k4 = (i & 63) << 2;
                    float4 v = __ldcg((const float4*)&hsrc[(size_t)(r0 + rr) * H + k4]);
                    *(float4*)&sH[rr * SH_STRIDE + k4] = v;
                }
            }
            __syncthreads();
        }
    }
}

// -------- projection + 96-step diagonal forecast, fused --------
__global__ void forecast_kernel(
    const float* __restrict__ h2, const float* __restrict__ Wp,
    const float* __restrict__ bp, const float* __restrict__ C,
    const float* __restrict__ rld, const float* __restrict__ rtd,
    const float* __restrict__ rg_, const float* __restrict__ om,
    float* __restrict__ out)
{
    const int b = blockIdx.x;
    const int d = threadIdx.x;
    __shared__ float sh[H];
    for (int i = d; i < H; i += 32) sh[i] = h2[(size_t)b * H + i];
    __syncthreads();

    float s[NSTATE];
#pragma unroll
    for (int st = 0; st < NSTATE; st++) {
        const float* w = Wp + (size_t)(d * NSTATE + st) * H;
        float acc = bp[d * NSTATE + st];
        for (int k = 0; k < H; k += 4) {
            float4 wv = *(const float4*)(w + k);
            acc += sh[k] * wv.x + sh[k + 1] * wv.y + sh[k + 2] * wv.z + sh[k + 3] * wv.w;
        }
        s[st] = acc;
    }

    float al = 1.f / (1.f + expf(-rld[d])) * 0.15f + 0.85f;
    float at = 1.f / (1.f + expf(-rtd[d])) * 0.25f + 0.70f;
    float gg = 1.f / (1.f + expf(-rg_[d])) * 0.20f + 0.80f;
    float cc = cosf(om[d]), sn = sinf(om[d]);
    float r00 = gg * cc, r01 = -gg * sn, r10 = gg * sn, r11 = gg * cc;
    float C0 = C[d * 4 + 0], C1 = C[d * 4 + 1], C2 = C[d * 4 + 2], C3 = C[d * 4 + 3];

    for (int p = 0; p < PRED; p++) {
        float n0 = s[0] * al;
        float n1 = s[1] * at;
        float n2 = s[2] * r00 + s[3] * r10;
        float n3 = s[2] * r01 + s[3] * r11;
        s[0] = n0; s[1] = n1; s[2] = n2; s[3] = n3;
        out[((size_t)b * PRED + p) * D_OUT + d] = C0 * n0 + C1 * n1 + C2 * n2 + C3 * n3;
    }
}

extern "C" void kernel_launch(void* const* d_in, const int* in_sizes, int n_in,
                              void* d_out, int out_size)
{
    const float* x    = (const float*)d_in[0];
    const float* Wih0 = (const float*)d_in[1];
    const float* Whh0 = (const float*)d_in[2];
    const float* bih0 = (const float*)d_in[3];
    const float* bhh0 = (const float*)d_in[4];
    const float* Wih1 = (const float*)d_in[5];
    const float* Whh1 = (const float*)d_in[6];
    const float* bih1 = (const float*)d_in[7];
    const float* bhh1 = (const float*)d_in[8];
    const float* Wp   = (const float*)d_in[9];
    const float* bp   = (const float*)d_in[10];
    const float* C    = (const float*)d_in[11];
    const float* rld  = (const float*)d_in[12];
    const float* rtd  = (const float*)d_in[13];
    const float* rg   = (const float*)d_in[14];
    const float* om   = (const float*)d_in[15];
    float* out = (float*)d_out;

    float *xp, *h1s, *h2;
    cudaGetSymbolAddress((void**)&xp, g_xp);
    cudaGetSymbolAddress((void**)&h1s, g_h1s);
    cudaGetSymbolAddress((void**)&h2, g_h2);

    cudaFuncSetAttribute(gru_layer, cudaFuncAttributeMaxDynamicSharedMemorySize, SMEM_BYTES);

    dim3 gg(G3 / 64, (B * S) / 128);

    gemm_nt_bias<<<gg, 256>>>(x, Wih0, bih0, xp, B * S, G3, IN_F);
    gru_layer<<<GRU_CTAS, 128, SMEM_BYTES>>>(xp, Whh0, bhh0, h1s, nullptr);
    gemm_nt_bias<<<gg, 256>>>(h1s, Wih1, bih1, xp, B * S, G3, H);
    gru_layer<<<GRU_CTAS, 128, SMEM_BYTES>>>(xp, Whh1, bhh1, nullptr, h2);
    forecast_kernel<<<B, 32>>>(h2, Wp, bp, C, rld, rtd, rg, om, out);
}